// round 13
// baseline (speedup 1.0000x reference)
#include <cuda_runtime.h>
#include <cuda_bf16.h>

#define TT 2048
#define BB 4096
#define NTH 256
#define NCTA 64

typedef unsigned long long u64;
typedef unsigned int u32;
typedef unsigned short u16;

__device__ float g_rT[(size_t)TT * BB];   // returns transposed [t][b]
__device__ float g_lT[(size_t)TT * BB];   // log_rv  transposed [t][b]

static __device__ __forceinline__ u64 pk2(float x, float y){
    u64 r; asm("mov.b64 %0,{%1,%2};" : "=l"(r) : "f"(x), "f"(y)); return r;
}
static __device__ __forceinline__ void up2(u64 v, float &x, float &y){
    asm("mov.b64 {%0,%1},%2;" : "=f"(x), "=f"(y) : "l"(v));
}
static __device__ __forceinline__ u64 add2(u64 a, u64 b){
    u64 d; asm("add.rn.f32x2 %0,%1,%2;" : "=l"(d) : "l"(a), "l"(b)); return d;
}
static __device__ __forceinline__ float pick4(float a, float b, float c, float d, int s){
    float x = (s & 1) ? b : a;
    float y = (s & 1) ? d : c;
    return (s & 2) ? y : x;
}
static __device__ __forceinline__ float pick8(const float* v, int s){
    float x = pick4(v[0], v[1], v[2], v[3], s & 3);
    float y = pick4(v[4], v[5], v[6], v[7], s & 3);
    return (s & 4) ? y : x;
}
static __device__ __forceinline__ u32 bfpack(float lo, float hi){
    u32 r; asm("cvt.rn.bf16x2.f32 %0, %1, %2;" : "=r"(r) : "f"(hi), "f"(lo)); return r;
}
static __device__ __forceinline__ u16 bf1(float x){
    __nv_bfloat16 b = __float2bfloat16(x);
    return *reinterpret_cast<u16*>(&b);
}
static __device__ __forceinline__ void mma16816(
    float &c0, float &c1, float &c2, float &c3,
    u32 a0, u32 a1, u32 a2, u32 a3, u32 b0, u32 b1)
{
    asm("mma.sync.aligned.m16n8k16.row.col.f32.bf16.bf16.f32 "
        "{%0,%1,%2,%3},{%4,%5,%6,%7},{%8,%9},{%0,%1,%2,%3};"
        : "+f"(c0), "+f"(c1), "+f"(c2), "+f"(c3)
        : "r"(a0), "r"(a1), "r"(a2), "r"(a3), "r"(b0), "r"(b1));
}

// ---- prologue: [B][T] -> [T][B] transpose for both inputs ----
__global__ void transpose_kernel(const float* __restrict__ retn,
                                 const float* __restrict__ lrv)
{
    __shared__ float tile[32][33];
    const float* src = blockIdx.z ? lrv : retn;
    float* dst = blockIdx.z ? g_lT : g_rT;
    const int t0 = blockIdx.x * 32, b0 = blockIdx.y * 32;
    const int tx = threadIdx.x, ty = threadIdx.y;
    #pragma unroll
    for (int i = 0; i < 32; i += 8)
        tile[ty + i][tx] = src[(size_t)(b0 + ty + i) * TT + t0 + tx];
    __syncthreads();
    #pragma unroll
    for (int i = 0; i < 32; i += 8)
        dst[(size_t)(t0 + ty + i) * BB + b0 + tx] = tile[tx][ty + i];
}

__global__ __launch_bounds__(NTH, 1)
void garch_pinn_kernel(
    const float* __restrict__ omega_p, const float* __restrict__ beta_p,
    const float* __restrict__ tau1_p, const float* __restrict__ tau2_p,
    const float* __restrict__ gamma_p, const float* __restrict__ xi_p,
    const float* __restrict__ phi_p, const float* __restrict__ d1_p,
    const float* __restrict__ d2_p, const float* __restrict__ mu_p,
    const float* __restrict__ W1, const float* __restrict__ b1,
    const float* __restrict__ W2, const float* __restrict__ b2,
    const float* __restrict__ W3, const float* __restrict__ b3_p,
    float* __restrict__ out)
{
    // bf16 h tile per warp: [chain 0..7][i 0..63 pad 72]
    __shared__ u16 hsm[8][8][72];                    // 9 KB
    // output staging per warp: rows 0-7 enh(arr0), 8-15 z(arr2), 16-23 u(arr3)
    __shared__ float obuf[8][24][33];                // 25 KB

    const int tid = threadIdx.x;
    const int w = tid >> 5;
    const int l = tid & 31;
    const int r = l >> 2;          // mma row group / b-chain
    const int kq = (l & 3) * 2;    // mma k / col pair base

    // ---- A fragments (A[m][k] = W2[k][m]) preloaded ----
    u32 afr[4][4][4];
    #pragma unroll
    for (int mt = 0; mt < 4; mt++) {
        #pragma unroll
        for (int kt = 0; kt < 4; kt++) {
            const int m0 = 16 * mt + r, k0 = 16 * kt + kq;
            afr[mt][kt][0] = bfpack(W2[k0 * 64 + m0],           W2[(k0 + 1) * 64 + m0]);
            afr[mt][kt][1] = bfpack(W2[k0 * 64 + m0 + 8],       W2[(k0 + 1) * 64 + m0 + 8]);
            afr[mt][kt][2] = bfpack(W2[(k0 + 8) * 64 + m0],     W2[(k0 + 9) * 64 + m0]);
            afr[mt][kt][3] = bfpack(W2[(k0 + 8) * 64 + m0 + 8], W2[(k0 + 9) * 64 + m0 + 8]);
        }
    }
    float b2lo[4], b2hi[4], w3lo[4], w3hi[4];
    #pragma unroll
    for (int mt = 0; mt < 4; mt++) {
        b2lo[mt] = b2[16 * mt + r];     b2hi[mt] = b2[16 * mt + r + 8];
        w3lo[mt] = W3[16 * mt + r];     w3hi[mt] = W3[16 * mt + r + 8];
    }

    const float w1a0 = W1[0 * 64 + l],      w1a1 = W1[1 * 64 + l],      w1a2 = W1[2 * 64 + l];
    const float w1b0 = W1[0 * 64 + l + 32], w1b1 = W1[1 * 64 + l + 32], w1b2 = W1[2 * 64 + l + 32];
    const float b1a = b1[l], b1b = b1[l + 32];

    const float omega = *omega_p, beta = *beta_p, tau1 = *tau1_p, tau2 = *tau2_p;
    const float gam = *gamma_p, xi = *xi_p, phi = *phi_p;
    const float d1 = *d1_p, d2 = *d2_p, mu = *mu_p, b3 = *b3_p;

    // this warp's 8 batch chains
    const int bg = blockIdx.x * 64 + w * 8;
    const long BT = (long)BB * TT;

    float lh[8];
    {
        const float4* lv = reinterpret_cast<const float4*>(g_lT + bg);
        float4 a = lv[0], b = lv[1];
        lh[0] = a.x; lh[1] = a.y; lh[2] = a.z; lh[3] = a.w;
        lh[4] = b.x; lh[5] = b.y; lh[6] = b.z; lh[7] = b.w;
    }

    u16* hw = &hsm[w][0][0];
    const u16* browp = &hsm[w][r][kq];
    float* obw = &obuf[w][0][0];

    for (int t = 0; t < TT; t++) {
        // ---- inputs: 4 uniform LDG.128 from transposed layout ----
        float rcur[8], lcur[8];
        {
            const float4* rv = reinterpret_cast<const float4*>(g_rT + (size_t)t * BB + bg);
            const float4* lv = reinterpret_cast<const float4*>(g_lT + (size_t)t * BB + bg);
            float4 a = rv[0], b = rv[1];
            rcur[0] = a.x; rcur[1] = a.y; rcur[2] = a.z; rcur[3] = a.w;
            rcur[4] = b.x; rcur[5] = b.y; rcur[6] = b.z; rcur[7] = b.w;
            float4 c = lv[0], d = lv[1];
            lcur[0] = c.x; lcur[1] = c.y; lcur[2] = c.z; lcur[3] = c.w;
            lcur[4] = d.x; lcur[5] = d.y; lcur[6] = d.z; lcur[7] = d.w;
        }

        // ---- measurement (exact fp32) ----
        float z[8], u[8], z2m1[8];
        #pragma unroll
        for (int b = 0; b < 8; b++) {
            float e = __expf(-0.5f * lh[b]);
            z[b] = (rcur[b] - mu) * e;
            z2m1[b] = z[b] * z[b] - 1.0f;
            float s = xi + phi * lh[b] + d1 * z[b] + d2 * z2m1[b];
            u[b] = lcur[b] - s;
        }

        // ---- layer 1: rows l and l+32, 8 chains; bf16 tile ----
        #pragma unroll
        for (int b = 0; b < 8; b++) {
            float t0 = fmaf(w1a0, lh[b], b1a);
            t0 = fmaf(w1a1, z[b], t0);
            t0 = fmaf(w1a2, u[b], t0);
            hw[b * 72 + l] = bf1(fmaxf(t0, 0.0f));
            float t1 = fmaf(w1b0, lh[b], b1b);
            t1 = fmaf(w1b1, z[b], t1);
            t1 = fmaf(w1b2, u[b], t1);
            hw[b * 72 + l + 32] = bf1(fmaxf(t1, 0.0f));
        }

        // stage z (lanes 8-15) and u (lanes 16-23)
        if (l >= 8 && l < 24) {
            const int ch = l & 7;
            float v = (l < 16) ? pick8(z, ch) : pick8(u, ch);
            obw[l * 33 + (t & 31)] = v;
        }
        __syncwarp();

        // ---- B fragments ----
        u32 bfr[4][2];
        #pragma unroll
        for (int kt = 0; kt < 4; kt++) {
            bfr[kt][0] = *reinterpret_cast<const u32*>(browp + 16 * kt);
            bfr[kt][1] = *reinterpret_cast<const u32*>(browp + 16 * kt + 8);
        }

        // ---- layer 2 on tensor pipe (full N=8) ----
        float cf[4][4];
        #pragma unroll
        for (int mt = 0; mt < 4; mt++) {
            cf[mt][0] = b2lo[mt]; cf[mt][1] = b2lo[mt];
            cf[mt][2] = b2hi[mt]; cf[mt][3] = b2hi[mt];
            #pragma unroll
            for (int kt = 0; kt < 4; kt++)
                mma16816(cf[mt][0], cf[mt][1], cf[mt][2], cf[mt][3],
                         afr[mt][kt][0], afr[mt][kt][1], afr[mt][kt][2], afr[mt][kt][3],
                         bfr[kt][0], bfr[kt][1]);
        }

        // ---- layer 3 epilogue ----
        float pe = 0.0f, po = 0.0f;
        #pragma unroll
        for (int mt = 0; mt < 4; mt++) {
            pe = fmaf(fmaxf(cf[mt][0], 0.0f), w3lo[mt], pe);
            pe = fmaf(fmaxf(cf[mt][2], 0.0f), w3hi[mt], pe);
            po = fmaf(fmaxf(cf[mt][1], 0.0f), w3lo[mt], po);
            po = fmaf(fmaxf(cf[mt][3], 0.0f), w3hi[mt], po);
        }
        u64 pair = pk2(pe, po);
        #pragma unroll
        for (int s = 4; s <= 16; s <<= 1)
            pair = add2(pair, __shfl_xor_sync(0xffffffffu, pair, s));
        const int base = l & ~3;
        float tot[8];
        #pragma unroll
        for (int j = 0; j < 4; j++) {
            u64 tp = __shfl_sync(0xffffffffu, pair, base + j);
            up2(tp, tot[2 * j], tot[2 * j + 1]);
        }

        float enh[8];
        #pragma unroll
        for (int b = 0; b < 8; b++)
            enh[b] = fmaf(0.01f, tot[b] + b3, lh[b]);

        if (l < 8) obw[l * 33 + (t & 31)] = pick8(enh, l);

        // ---- GARCH recurrence ----
        #pragma unroll
        for (int b = 0; b < 8; b++) {
            float nl = fmaf(beta, enh[b], omega);
            nl = fmaf(tau1, z[b], nl);
            nl = fmaf(tau2, z2m1[b], nl);
            lh[b] = fmaf(gam, u[b], nl);
        }

        // ---- flush every 32 steps: 24 rows (enh, z, u) ----
        if ((t & 31) == 31) {
            const int t0 = t - 31;
            #pragma unroll
            for (int q = 0; q < 24; q++) {
                const int arr = (q < 8) ? 0 : (q < 16) ? 2 : 3;
                const int ch = q & 7;
                out[(long)arr * BT + (long)(bg + ch) * TT + t0 + l] = obw[q * 33 + l];
            }
        }
        __syncwarp();
    }
}

extern "C" void kernel_launch(void* const* d_in, const int* in_sizes, int n_in,
                              void* d_out, int out_size)
{
    const float* retn = (const float*)d_in[0];
    const float* lrv  = (const float*)d_in[1];
    float* out = (float*)d_out;
    const size_t BT = (size_t)BB * TT;

    // prologue: transpose inputs to [T][B]
    transpose_kernel<<<dim3(TT / 32, BB / 32, 2), dim3(32, 8)>>>(retn, lrv);
    // arr1 (log_x) == log_rv exactly: device-to-device copy
    cudaMemcpyAsync(out + BT, lrv, BT * sizeof(float), cudaMemcpyDeviceToDevice);

    garch_pinn_kernel<<<NCTA, NTH>>>(
        (const float*)d_in[2],  (const float*)d_in[3],
        (const float*)d_in[4],  (const float*)d_in[5],
        (const float*)d_in[6],  (const float*)d_in[7],
        (const float*)d_in[8],  (const float*)d_in[9],
        (const float*)d_in[10], (const float*)d_in[11],
        (const float*)d_in[12], (const float*)d_in[13],
        (const float*)d_in[14], (const float*)d_in[15],
        (const float*)d_in[16], (const float*)d_in[17],
        out);
}

// round 14
// speedup vs baseline: 1.7369x; 1.7369x over previous
#include <cuda_runtime.h>
#include <cuda_bf16.h>

#define TT 2048
#define BB 4096
#define NTH 256
#define NCTA 128

typedef unsigned long long u64;
typedef unsigned int u32;
typedef unsigned short u16;

static __device__ __forceinline__ u64 pk2(float x, float y){
    u64 r; asm("mov.b64 %0,{%1,%2};" : "=l"(r) : "f"(x), "f"(y)); return r;
}
static __device__ __forceinline__ void up2(u64 v, float &x, float &y){
    asm("mov.b64 {%0,%1},%2;" : "=f"(x), "=f"(y) : "l"(v));
}
static __device__ __forceinline__ u64 add2(u64 a, u64 b){
    u64 d; asm("add.rn.f32x2 %0,%1,%2;" : "=l"(d) : "l"(a), "l"(b)); return d;
}
static __device__ __forceinline__ float pick4(float a, float b, float c, float d, int s){
    float x = (s & 1) ? b : a;
    float y = (s & 1) ? d : c;
    return (s & 2) ? y : x;
}
static __device__ __forceinline__ u32 bfpack(float lo, float hi){
    u32 r; asm("cvt.rn.bf16x2.f32 %0, %1, %2;" : "=r"(r) : "f"(hi), "f"(lo)); return r;
}
static __device__ __forceinline__ u16 bf1(float x){
    __nv_bfloat16 b = __float2bfloat16(x);
    return *reinterpret_cast<u16*>(&b);
}
static __device__ __forceinline__ void mma16816(
    float &c0, float &c1, float &c2, float &c3,
    u32 a0, u32 a1, u32 a2, u32 a3, u32 b0, u32 b1)
{
    asm("mma.sync.aligned.m16n8k16.row.col.f32.bf16.bf16.f32 "
        "{%0,%1,%2,%3},{%4,%5,%6,%7},{%8,%9},{%0,%1,%2,%3};"
        : "+f"(c0), "+f"(c1), "+f"(c2), "+f"(c3)
        : "r"(a0), "r"(a1), "r"(a2), "r"(a3), "r"(b0), "r"(b1));
}

__global__ __launch_bounds__(NTH, 1)
void garch_pinn_kernel(
    const float* __restrict__ returns, const float* __restrict__ log_rv,
    const float* __restrict__ omega_p, const float* __restrict__ beta_p,
    const float* __restrict__ tau1_p, const float* __restrict__ tau2_p,
    const float* __restrict__ gamma_p, const float* __restrict__ xi_p,
    const float* __restrict__ phi_p, const float* __restrict__ d1_p,
    const float* __restrict__ d2_p, const float* __restrict__ mu_p,
    const float* __restrict__ W1, const float* __restrict__ b1,
    const float* __restrict__ W2, const float* __restrict__ b2,
    const float* __restrict__ W3, const float* __restrict__ b3_p,
    float* __restrict__ out)
{
    // bf16 h tile per warp: [chain][i], row padded to 80 u16
    __shared__ u16 hsm[8][4][80];                     // 5 KB
    // per-warp output staging: rows 0-3 enh(arr0), 8-11 z(arr2), 12-15 u(arr3)
    __shared__ float obuf[8][16][33];

    const int tid = threadIdx.x;
    const int w = tid >> 5;
    const int l = tid & 31;
    const int r = l >> 2;          // mma fragment row group
    const int kq = (l & 3) * 2;    // mma fragment k / col pair base

    // ---- A fragments (A[m][k] = W2[k][m]) preloaded ----
    u32 afr[4][4][4];
    #pragma unroll
    for (int mt = 0; mt < 4; mt++) {
        #pragma unroll
        for (int kt = 0; kt < 4; kt++) {
            const int m0 = 16 * mt + r, k0 = 16 * kt + kq;
            afr[mt][kt][0] = bfpack(W2[k0 * 64 + m0],           W2[(k0 + 1) * 64 + m0]);
            afr[mt][kt][1] = bfpack(W2[k0 * 64 + m0 + 8],       W2[(k0 + 1) * 64 + m0 + 8]);
            afr[mt][kt][2] = bfpack(W2[(k0 + 8) * 64 + m0],     W2[(k0 + 9) * 64 + m0]);
            afr[mt][kt][3] = bfpack(W2[(k0 + 8) * 64 + m0 + 8], W2[(k0 + 9) * 64 + m0 + 8]);
        }
    }
    float b2lo[4], b2hi[4], w3lo[4], w3hi[4];
    #pragma unroll
    for (int mt = 0; mt < 4; mt++) {
        b2lo[mt] = b2[16 * mt + r];     b2hi[mt] = b2[16 * mt + r + 8];
        w3lo[mt] = W3[16 * mt + r];     w3hi[mt] = W3[16 * mt + r + 8];
    }

    const float w1a0 = W1[0 * 64 + l],      w1a1 = W1[1 * 64 + l],      w1a2 = W1[2 * 64 + l];
    const float w1b0 = W1[0 * 64 + l + 32], w1b1 = W1[1 * 64 + l + 32], w1b2 = W1[2 * 64 + l + 32];
    const float b1a = b1[l], b1b = b1[l + 32];

    const float omega = *omega_p, beta = *beta_p, tau1 = *tau1_p, tau2 = *tau2_p;
    const float gam = *gamma_p, xi = *xi_p, phi = *phi_p;
    const float d1 = *d1_p, d2 = *d2_p, mu = *mu_p, b3 = *b3_p;
    const float beta001 = beta * 0.01f;   // lh' = base + beta001*tot

    // this warp's 4 batch chains ([B][T] layout keeps lines L1-resident)
    const long bg = (long)blockIdx.x * 32 + w * 4;
    const float* rp = returns + bg * TT;
    const float* lp = log_rv + bg * TT;
    const long BT = (long)BB * TT;

    float lh[4];
    #pragma unroll
    for (int b = 0; b < 4; b++) lh[b] = lp[b * TT];

    u16* hw = &hsm[w][0][0];
    const u16* browp = &hsm[w][r & 3][kq];
    const bool bactive = (l < 16);
    float* obw = &obuf[w][0][0];

    // preload step-0 inputs
    float rcur[4], lcur[4];
    #pragma unroll
    for (int b = 0; b < 4; b++) { rcur[b] = rp[b * TT]; lcur[b] = lp[b * TT]; }

    for (int t = 0; t < TT; t++) {
        // ---- measurement (exact fp32) ----
        float z[4], u[4], base[4];
        #pragma unroll
        for (int b = 0; b < 4; b++) {
            float e = __expf(-0.5f * lh[b]);
            z[b] = (rcur[b] - mu) * e;
            float z2m1 = z[b] * z[b] - 1.0f;
            float s = xi + phi * lh[b] + d1 * z[b] + d2 * z2m1;
            u[b] = lcur[b] - s;          // log_x == lcur (emitted via D2D copy)
            // recurrence base: all but the NN term
            float nb = fmaf(beta, lh[b], omega);
            nb = fmaf(tau1, z[b], nb);
            nb = fmaf(tau2, z2m1, nb);
            nb = fmaf(gam, u[b], nb);
            base[b] = fmaf(beta001, b3, nb);
        }

        // ---- layer 1 (fp32) -> bf16 tile ----
        #pragma unroll
        for (int c = 0; c < 4; c++) {
            float t0 = fmaf(w1a0, lh[c], b1a);
            t0 = fmaf(w1a1, z[c], t0);
            t0 = fmaf(w1a2, u[c], t0);
            hw[c * 80 + l] = bf1(fmaxf(t0, 0.0f));
            float t1 = fmaf(w1b0, lh[c], b1b);
            t1 = fmaf(w1b1, z[c], t1);
            t1 = fmaf(w1b2, u[c], t1);
            hw[c * 80 + l + 32] = bf1(fmaxf(t1, 0.0f));
        }

        // stage z (lanes 8-11) and u (lanes 12-15)
        if (l >= 8 && l < 16) {
            const int bsel = l & 3;
            float v_z = pick4(z[0], z[1], z[2], z[3], bsel);
            float v_u = pick4(u[0], u[1], u[2], u[3], bsel);
            obw[l * 33 + (t & 31)] = (l < 12) ? v_z : v_u;
        }
        __syncwarp();

        // ---- B fragments ----
        u32 bfr[4][2];
        #pragma unroll
        for (int kt = 0; kt < 4; kt++) {
            u32 b01 = 0, b23 = 0;
            if (bactive) {
                b01 = *reinterpret_cast<const u32*>(browp + 16 * kt);
                b23 = *reinterpret_cast<const u32*>(browp + 16 * kt + 8);
            }
            bfr[kt][0] = b01; bfr[kt][1] = b23;
        }

        // ---- prefetch next-step inputs (hidden under tensor work) ----
        const int tn = (t + 1 < TT) ? t + 1 : t;
        float rnxt[4], lnxt[4];
        #pragma unroll
        for (int b = 0; b < 4; b++) { rnxt[b] = rp[b * TT + tn]; lnxt[b] = lp[b * TT + tn]; }

        // ---- layer 2 on tensor pipe: split kt chains (2-deep instead of 4) ----
        float cf[4][4];
        #pragma unroll
        for (int mt = 0; mt < 4; mt++) {
            float d0 = b2lo[mt], d1r = b2lo[mt], d2r = b2hi[mt], d3 = b2hi[mt];
            float e0 = 0.f, e1 = 0.f, e2 = 0.f, e3 = 0.f;
            mma16816(d0, d1r, d2r, d3,
                     afr[mt][0][0], afr[mt][0][1], afr[mt][0][2], afr[mt][0][3],
                     bfr[0][0], bfr[0][1]);
            mma16816(e0, e1, e2, e3,
                     afr[mt][1][0], afr[mt][1][1], afr[mt][1][2], afr[mt][1][3],
                     bfr[1][0], bfr[1][1]);
            mma16816(d0, d1r, d2r, d3,
                     afr[mt][2][0], afr[mt][2][1], afr[mt][2][2], afr[mt][2][3],
                     bfr[2][0], bfr[2][1]);
            mma16816(e0, e1, e2, e3,
                     afr[mt][3][0], afr[mt][3][1], afr[mt][3][2], afr[mt][3][3],
                     bfr[3][0], bfr[3][1]);
            cf[mt][0] = d0 + e0; cf[mt][1] = d1r + e1;
            cf[mt][2] = d2r + e2; cf[mt][3] = d3 + e3;
        }

        // ---- layer 3 epilogue: relu + W3 dot ----
        float pe = 0.0f, po = 0.0f;
        #pragma unroll
        for (int mt = 0; mt < 4; mt++) {
            pe = fmaf(fmaxf(cf[mt][0], 0.0f), w3lo[mt], pe);
            pe = fmaf(fmaxf(cf[mt][2], 0.0f), w3hi[mt], pe);
            po = fmaf(fmaxf(cf[mt][1], 0.0f), w3lo[mt], po);
            po = fmaf(fmaxf(cf[mt][3], 0.0f), w3hi[mt], po);
        }
        u64 pair = pk2(pe, po);
        #pragma unroll
        for (int s = 4; s <= 16; s <<= 1)
            pair = add2(pair, __shfl_xor_sync(0xffffffffu, pair, s));
        const int base4 = l & ~3;
        u64 t01 = __shfl_sync(0xffffffffu, pair, base4);
        u64 t23 = __shfl_sync(0xffffffffu, pair, base4 + 1);
        float tot[4];
        up2(t01, tot[0], tot[1]);
        up2(t23, tot[2], tot[3]);

        // stage enh (lanes 0-3); enh recomputed from lh (1 fma each)
        if (l < 4) obw[l * 33 + (t & 31)] = fmaf(0.01f, tot[l] + b3, lh[l]);

        // ---- recurrence: single fma after reduction ----
        #pragma unroll
        for (int b = 0; b < 4; b++) {
            lh[b] = fmaf(beta001, tot[b], base[b]);
            rcur[b] = rnxt[b];
            lcur[b] = lnxt[b];
        }

        // ---- flush every 32 steps: 12 used rows (enh, z, u) ----
        if ((t & 31) == 31) {
            const int t0 = t - 31;
            #pragma unroll
            for (int q = 0; q < 12; q++) {
                const int sr = (q < 4) ? q : q + 4;          // staging row
                const int arr = (q < 4) ? 0 : (q < 8) ? 2 : 3;
                const int bsel = q & 3;
                out[(long)arr * BT + (bg + bsel) * TT + t0 + l] = obw[sr * 33 + l];
            }
        }
        __syncwarp();
    }
}

extern "C" void kernel_launch(void* const* d_in, const int* in_sizes, int n_in,
                              void* d_out, int out_size)
{
    const float* retn = (const float*)d_in[0];
    const float* lrv  = (const float*)d_in[1];
    float* out = (float*)d_out;
    const size_t BT = (size_t)BB * TT;

    // arr1 (log_x) == log_rv exactly: device-to-device copy
    cudaMemcpyAsync(out + BT, lrv, BT * sizeof(float), cudaMemcpyDeviceToDevice);

    garch_pinn_kernel<<<NCTA, NTH>>>(
        retn, lrv,
        (const float*)d_in[2],  (const float*)d_in[3],
        (const float*)d_in[4],  (const float*)d_in[5],
        (const float*)d_in[6],  (const float*)d_in[7],
        (const float*)d_in[8],  (const float*)d_in[9],
        (const float*)d_in[10], (const float*)d_in[11],
        (const float*)d_in[12], (const float*)d_in[13],
        (const float*)d_in[14], (const float*)d_in[15],
        (const float*)d_in[16], (const float*)d_in[17],
        out);
}

// round 15
// speedup vs baseline: 1.8284x; 1.0527x over previous
#include <cuda_runtime.h>
#include <cuda_bf16.h>

#define TT 2048
#define BB 4096
#define NTH 256
#define NCTA 128

typedef unsigned long long u64;
typedef unsigned int u32;
typedef unsigned short u16;

static __device__ __forceinline__ u64 pk2(float x, float y){
    u64 r; asm("mov.b64 %0,{%1,%2};" : "=l"(r) : "f"(x), "f"(y)); return r;
}
static __device__ __forceinline__ void up2(u64 v, float &x, float &y){
    asm("mov.b64 {%0,%1},%2;" : "=f"(x), "=f"(y) : "l"(v));
}
static __device__ __forceinline__ u64 add2(u64 a, u64 b){
    u64 d; asm("add.rn.f32x2 %0,%1,%2;" : "=l"(d) : "l"(a), "l"(b)); return d;
}
static __device__ __forceinline__ float pick4(float a, float b, float c, float d, int s){
    float x = (s & 1) ? b : a;
    float y = (s & 1) ? d : c;
    return (s & 2) ? y : x;
}
static __device__ __forceinline__ u32 bfpack(float lo, float hi){
    u32 r; asm("cvt.rn.bf16x2.f32 %0, %1, %2;" : "=r"(r) : "f"(hi), "f"(lo)); return r;
}
static __device__ __forceinline__ void mma16816(
    float &c0, float &c1, float &c2, float &c3,
    u32 a0, u32 a1, u32 a2, u32 a3, u32 b0, u32 b1)
{
    asm("mma.sync.aligned.m16n8k16.row.col.f32.bf16.bf16.f32 "
        "{%0,%1,%2,%3},{%4,%5,%6,%7},{%8,%9},{%0,%1,%2,%3};"
        : "+f"(c0), "+f"(c1), "+f"(c2), "+f"(c3)
        : "r"(a0), "r"(a1), "r"(a2), "r"(a3), "r"(b0), "r"(b1));
}

__global__ __launch_bounds__(NTH, 1)
void garch_pinn_kernel(
    const float* __restrict__ returns, const float* __restrict__ log_rv,
    const float* __restrict__ omega_p, const float* __restrict__ beta_p,
    const float* __restrict__ tau1_p, const float* __restrict__ tau2_p,
    const float* __restrict__ gamma_p, const float* __restrict__ xi_p,
    const float* __restrict__ phi_p, const float* __restrict__ d1_p,
    const float* __restrict__ d2_p, const float* __restrict__ mu_p,
    const float* __restrict__ W1, const float* __restrict__ b1,
    const float* __restrict__ W2, const float* __restrict__ b2,
    const float* __restrict__ W3, const float* __restrict__ b3_p,
    float* __restrict__ out)
{
    // bf16 h tile per warp: [chain][i], row padded to 80 u16
    __shared__ u16 hsm[8][4][80];                     // 5 KB
    // per-warp output staging: [warp][arr*4+b][33]
    __shared__ float obuf[8][16][33];

    const int tid = threadIdx.x;
    const int w = tid >> 5;
    const int l = tid & 31;
    const int r = l >> 2;          // mma fragment row group
    const int kq = (l & 3) * 2;    // mma fragment k / col pair base

    // ---- A fragments (A[m][k] = W2[k][m]) preloaded ----
    u32 afr[4][4][4];
    #pragma unroll
    for (int mt = 0; mt < 4; mt++) {
        #pragma unroll
        for (int kt = 0; kt < 4; kt++) {
            const int m0 = 16 * mt + r, k0 = 16 * kt + kq;
            afr[mt][kt][0] = bfpack(W2[k0 * 64 + m0],           W2[(k0 + 1) * 64 + m0]);
            afr[mt][kt][1] = bfpack(W2[k0 * 64 + m0 + 8],       W2[(k0 + 1) * 64 + m0 + 8]);
            afr[mt][kt][2] = bfpack(W2[(k0 + 8) * 64 + m0],     W2[(k0 + 9) * 64 + m0]);
            afr[mt][kt][3] = bfpack(W2[(k0 + 8) * 64 + m0 + 8], W2[(k0 + 9) * 64 + m0 + 8]);
        }
    }
    float b2lo[4], b2hi[4], w3lo[4], w3hi[4];
    #pragma unroll
    for (int mt = 0; mt < 4; mt++) {
        b2lo[mt] = b2[16 * mt + r];     b2hi[mt] = b2[16 * mt + r + 8];
        w3lo[mt] = W3[16 * mt + r];     w3hi[mt] = W3[16 * mt + r + 8];
    }

    // layer-1 constants: lane computes rows 2l and 2l+1 (adjacent -> packed STS.32)
    const float w1a0 = W1[0 * 64 + 2 * l],     w1a1 = W1[1 * 64 + 2 * l],     w1a2 = W1[2 * 64 + 2 * l];
    const float w1b0 = W1[0 * 64 + 2 * l + 1], w1b1 = W1[1 * 64 + 2 * l + 1], w1b2 = W1[2 * 64 + 2 * l + 1];
    const float b1a = b1[2 * l], b1b = b1[2 * l + 1];

    const float omega = *omega_p, beta = *beta_p, tau1 = *tau1_p, tau2 = *tau2_p;
    const float gam = *gamma_p, xi = *xi_p, phi = *phi_p;
    const float d1 = *d1_p, d2 = *d2_p, mu = *mu_p, b3 = *b3_p;
    const float beta001 = beta * 0.01f;
    const float C0 = fmaf(beta001, b3, omega);   // omega + 0.01*beta*b3

    // this warp's 4 batch chains ([B][T] layout: lines L1-resident for 32 steps)
    const long bg = (long)blockIdx.x * 32 + w * 4;
    const float* rp = returns + bg * TT;
    const float* lp = log_rv + bg * TT;
    const long BT = (long)BB * TT;

    float lh[4];
    #pragma unroll
    for (int b = 0; b < 4; b++) lh[b] = lp[b * TT];

    u16* hw = &hsm[w][0][0];
    const u16* browp = &hsm[w][r & 3][kq];   // lanes 16-31 duplicate chains 0-3
    float* obw = &obuf[w][0][0];

    float rcur[4], lcur[4];
    #pragma unroll
    for (int b = 0; b < 4; b++) { rcur[b] = rp[b * TT]; lcur[b] = lp[b * TT]; }

    for (int t = 0; t < TT; t++) {
        // ---- measurement (exact fp32) + recurrence base ----
        float z[4], u[4], base[4];
        #pragma unroll
        for (int b = 0; b < 4; b++) {
            float e = __expf(-0.5f * lh[b]);
            z[b] = (rcur[b] - mu) * e;
            float z2m1 = z[b] * z[b] - 1.0f;
            float s = xi + phi * lh[b] + d1 * z[b] + d2 * z2m1;
            u[b] = lcur[b] - s;              // log_x == lcur exactly
            float nb = fmaf(beta, lh[b], C0);
            nb = fmaf(tau1, z[b], nb);
            nb = fmaf(tau2, z2m1, nb);
            base[b] = fmaf(gam, u[b], nb);
        }

        // ---- layer 1 (fp32): rows 2l, 2l+1 -> packed bf16x2 STS.32 ----
        #pragma unroll
        for (int c = 0; c < 4; c++) {
            float t0 = fmaf(w1a0, lh[c], b1a);
            t0 = fmaf(w1a1, z[c], t0);
            t0 = fmaf(w1a2, u[c], t0);
            float t1 = fmaf(w1b0, lh[c], b1b);
            t1 = fmaf(w1b1, z[c], t1);
            t1 = fmaf(w1b2, u[c], t1);
            *reinterpret_cast<u32*>(hw + c * 80 + 2 * l) =
                bfpack(fmaxf(t0, 0.0f), fmaxf(t1, 0.0f));
        }

        // stage lx/z/u (lanes 4..15): arr = l>>2, batch = l&3
        {
            const int bsel = l & 3;
            float v_lx = pick4(lcur[0], lcur[1], lcur[2], lcur[3], bsel);
            float v_z  = pick4(z[0], z[1], z[2], z[3], bsel);
            float v_u  = pick4(u[0], u[1], u[2], u[3], bsel);
            float v = pick4(v_lx, v_lx, v_z, v_u, l >> 2);
            if (l >= 4 && l < 16) obw[l * 33 + (t & 31)] = v;
        }
        __syncwarp();

        // ---- B fragments (all lanes; cols 4-7 duplicate chains 0-3) ----
        u32 bfr[4][2];
        #pragma unroll
        for (int kt = 0; kt < 4; kt++) {
            bfr[kt][0] = *reinterpret_cast<const u32*>(browp + 16 * kt);
            bfr[kt][1] = *reinterpret_cast<const u32*>(browp + 16 * kt + 8);
        }

        // ---- prefetch next-step inputs (hidden under tensor work) ----
        const int tn = (t + 1 < TT) ? t + 1 : t;
        float rnxt[4], lnxt[4];
        #pragma unroll
        for (int b = 0; b < 4; b++) { rnxt[b] = rp[b * TT + tn]; lnxt[b] = lp[b * TT + tn]; }

        // ---- layer 2 on tensor pipe ----
        float cf[4][4];
        #pragma unroll
        for (int mt = 0; mt < 4; mt++) {
            cf[mt][0] = b2lo[mt]; cf[mt][1] = b2lo[mt];
            cf[mt][2] = b2hi[mt]; cf[mt][3] = b2hi[mt];
            #pragma unroll
            for (int kt = 0; kt < 4; kt++)
                mma16816(cf[mt][0], cf[mt][1], cf[mt][2], cf[mt][3],
                         afr[mt][kt][0], afr[mt][kt][1], afr[mt][kt][2], afr[mt][kt][3],
                         bfr[kt][0], bfr[kt][1]);
        }

        // ---- layer 3 epilogue: relu + W3 dot ----
        float pe = 0.0f, po = 0.0f;
        #pragma unroll
        for (int mt = 0; mt < 4; mt++) {
            pe = fmaf(fmaxf(cf[mt][0], 0.0f), w3lo[mt], pe);
            pe = fmaf(fmaxf(cf[mt][2], 0.0f), w3hi[mt], pe);
            po = fmaf(fmaxf(cf[mt][1], 0.0f), w3lo[mt], po);
            po = fmaf(fmaxf(cf[mt][3], 0.0f), w3hi[mt], po);
        }
        u64 pair = pk2(pe, po);
        #pragma unroll
        for (int s = 4; s <= 16; s <<= 1)
            pair = add2(pair, __shfl_xor_sync(0xffffffffu, pair, s));
        // class l&3 even -> (t0,t1); odd -> (t2,t3); one exchange completes all 4
        u64 other = __shfl_xor_sync(0xffffffffu, pair, 1);
        float mx, my, ox, oy;
        up2(pair, mx, my);
        up2(other, ox, oy);
        const bool oddc = (l & 1);
        float tot[4];
        tot[0] = oddc ? ox : mx;  tot[1] = oddc ? oy : my;
        tot[2] = oddc ? mx : ox;  tot[3] = oddc ? my : oy;

        // stage enh (lanes 0-3): needs OLD lh
        if (l < 4) obw[l * 33 + (t & 31)] = fmaf(0.01f, tot[l] + b3, lh[l]);

        // ---- recurrence: single fma ----
        #pragma unroll
        for (int b = 0; b < 4; b++) {
            lh[b] = fmaf(beta001, tot[b], base[b]);
            rcur[b] = rnxt[b];
            lcur[b] = lnxt[b];
        }

        // ---- flush every 32 steps ----
        if ((t & 31) == 31) {
            const int t0 = t - 31;
            #pragma unroll
            for (int q = 0; q < 16; q++) {
                const int arr = q >> 2, bsel = q & 3;
                out[(long)arr * BT + (bg + bsel) * TT + t0 + l] = obw[q * 33 + l];
            }
        }
        __syncwarp();
    }
}

extern "C" void kernel_launch(void* const* d_in, const int* in_sizes, int n_in,
                              void* d_out, int out_size)
{
    garch_pinn_kernel<<<NCTA, NTH>>>(
        (const float*)d_in[0],  (const float*)d_in[1],
        (const float*)d_in[2],  (const float*)d_in[3],
        (const float*)d_in[4],  (const float*)d_in[5],
        (const float*)d_in[6],  (const float*)d_in[7],
        (const float*)d_in[8],  (const float*)d_in[9],
        (const float*)d_in[10], (const float*)d_in[11],
        (const float*)d_in[12], (const float*)d_in[13],
        (const float*)d_in[14], (const float*)d_in[15],
        (const float*)d_in[16], (const float*)d_in[17],
        (float*)d_out);
}